// round 8
// baseline (speedup 1.0000x reference)
#include <cuda_runtime.h>
#include <cuda_fp16.h>
#include <cstdint>

// ---------------------------------------------------------------------------
// FlashMoERouter on GB300 (sm_103a) — HMMA mma.sync, fp16 2-way split.
// R8: R7 (B operands as pre-built MMA fragments via LDG from L2; X-only smem
//     ring; warp specialization) with the LO fragment window fixed to depth 4
//     (8 steps/iter mod 4 == 0 -> stationary slot phase).
// ---------------------------------------------------------------------------

#define SW128(o) ((o) ^ (((o) >> 3) & 0x70))

static constexpr int NTOK   = 16384;
static constexpr int DIM    = 4096;
static constexpr int NOUT   = 128;
static constexpr int NEXP   = 64;
static constexpr int MT     = 128;
static constexpr int KC     = 64;
static constexpr int NIT    = DIM / KC;     // 64

static constexpr int OFF_XH = 0;
static constexpr int OFF_XL = 16384;
static constexpr int BUF_B  = 32768;        // X-only stages
static constexpr int NSTAGE = 4;
static constexpr int OFF_BAR = NSTAGE * BUF_B;      // 131072
static constexpr int SMEM_SZ = OFF_BAR + 64;
static constexpr int EPI_LO  = 66048;               // lo[128][65] after sc[128][129]

// W fragment arrays (padded +1 chunk for tail prefetch)
// g_whf : hi wh, 16 n8-tiles/chunk, ks-pair packed (LDG.128): [65][16][2][512B]
// g_wlf : lo wl (cols 0..63), 8 n8/chunk, per-ks packed (LDG.64):  [65][8][4][256B]
// g_whf2: lo wh (cols 0..63), same layout as g_wlf
__device__ __align__(16) unsigned char g_whf[65 * 16384];
__device__ __align__(16) unsigned char g_wlf[65 * 8192];
__device__ __align__(16) unsigned char g_whf2[65 * 8192];

// ---------------- helpers ----------------
__device__ __forceinline__ uint32_t smem_u32(const void* p) {
    uint32_t a;
    asm("{ .reg .u64 t; cvta.to.shared.u64 t, %1; cvt.u32.u64 %0, t; }"
        : "=r"(a) : "l"(p));
    return a;
}
#define MBARRIER_INIT(addr, cnt) \
    asm volatile("mbarrier.init.shared.b64 [%0], %1;" :: "r"(addr), "r"(cnt) : "memory")
#define MBARRIER_ARRIVE(addr) \
    asm volatile("mbarrier.arrive.shared.b64 _, [%0];" :: "r"(addr) : "memory")
#define MBARRIER_WAIT_PARITY(addr, par) do {                                        \
    uint32_t _m = (addr), _p = (par), _d;                                           \
    asm volatile("{ .reg .pred p; mbarrier.try_wait.parity.acquire.cta.shared::cta.b64 p, [%1], %2; selp.b32 %0,1,0,p; }" \
                 : "=r"(_d) : "r"(_m), "r"(_p) : "memory");                         \
    if (!_d) {                                                                      \
        asm volatile("{ .reg .pred P;\n"                                            \
            "WL_%=: mbarrier.try_wait.parity.acquire.cta.shared::cta.b64 P, [%0], %1, 0x989680;\n" \
            "@P bra WD_%=;\n bra WL_%=;\n WD_%=: }"                                 \
            :: "r"(_m), "r"(_p) : "memory");                                        \
    }                                                                               \
} while (0)

__device__ __forceinline__ void ldsm4(uint32_t* r, uint32_t addr) {
    asm volatile("ldmatrix.sync.aligned.m8n8.x4.shared.b16 {%0,%1,%2,%3}, [%4];"
                 : "=r"(r[0]), "=r"(r[1]), "=r"(r[2]), "=r"(r[3]) : "r"(addr));
}
__device__ __forceinline__ void mma16816(float* d, const uint32_t* a,
                                         uint32_t b0, uint32_t b1) {
    asm volatile(
        "mma.sync.aligned.m16n8k16.row.col.f32.f16.f16.f32 "
        "{%0,%1,%2,%3}, {%4,%5,%6,%7}, {%8,%9}, {%0,%1,%2,%3};"
        : "+f"(d[0]), "+f"(d[1]), "+f"(d[2]), "+f"(d[3])
        : "r"(a[0]), "r"(a[1]), "r"(a[2]), "r"(a[3]), "r"(b0), "r"(b1));
}
__device__ __forceinline__ float wsum(float v) {
#pragma unroll
    for (int o = 16; o; o >>= 1) v += __shfl_xor_sync(0xffffffffu, v, o);
    return v;
}
__device__ __forceinline__ bool better(float v, int i, float w, int j) {
    return (v > w) || (v == w && i < j);
}

// ---------------- prep: split W into fragment-layout arrays ----------------
__global__ void prep_kernel(const float* __restrict__ gate_w,
                            const float* __restrict__ cap_w1) {
    int idx = blockIdx.x * blockDim.x + threadIdx.x;
    if (idx >= NOUT * DIM) return;
    int n = idx >> 12;
    int k = idx & (DIM - 1);
    float w = (n < NEXP) ? gate_w[n * DIM + k] : cap_w1[(n - NEXP) * DIM + k];
    __half wh = __float2half_rn(w);
    float res = (w - __half2float(wh)) * 2048.0f;
    __half wl = __float2half_rn(res);

    int chunk = k >> 6, kin = k & 63, ks = kin >> 4, kk = kin & 15;
    int n8 = n >> 3, ln = n & 7;
    int lane   = ln * 4 + ((kk & 7) >> 1);
    int inlane = ((kk & 8) ? 4 : 0) + (kk & 1) * 2;

    // hi (kspair-packed, 512B blocks)
    int haddr = chunk * 16384 + n8 * 1024 + (ks >> 1) * 512
              + lane * 16 + (ks & 1) * 8 + inlane;
    *(__half*)(g_whf + haddr) = wh;

    if (n < NEXP) {
        // lo (per-ks 256B blocks)
        int laddr = chunk * 8192 + n8 * 1024 + ks * 256 + lane * 8 + inlane;
        *(__half*)(g_wlf  + laddr) = wl;
        *(__half*)(g_whf2 + laddr) = wh;
    }
}

// ---------------- main kernel: 512 threads ----------------
__global__ void __launch_bounds__(512, 1)
router_kernel(const float* __restrict__ x,
              const float* __restrict__ cap_b1, const float* __restrict__ ln_g,
              const float* __restrict__ ln_b,   const float* __restrict__ cap_w2,
              const float* __restrict__ cap_b2, const float* __restrict__ temp,
              const float* __restrict__ usage,  float* __restrict__ out) {
    extern __shared__ char smem[];
    const uint32_t sb = smem_u32(smem);
    const int tid  = threadIdx.x;
    const int wid  = tid >> 5;
    const int lane = tid & 31;
    const int tok0 = blockIdx.x * MT;

    const uint32_t bFull  = sb + OFF_BAR;         // full[s]  at +8*s
    const uint32_t bEmpty = sb + OFF_BAR + 32;    // empty[s] at +8*s

    if (tid == 0) {
#pragma unroll
        for (int s = 0; s < NSTAGE; s++) {
            MBARRIER_INIT(bFull + 8 * s, 128);    // producer threads
            MBARRIER_INIT(bEmpty + 8 * s, 384);   // consumer threads
        }
    }
    __syncthreads();

    if (wid >= 12) {
        // ================= PRODUCER (wid 12..15, 128 threads) ===============
        const int pt = tid - 384;
        const int r0 = pt >> 2;
        const int kq = (pt & 3) * 16;
        const float* xrow0 = x + (size_t)(tok0 + r0) * DIM + kq;

        int pp = 1;
#pragma unroll 1
        for (int i = 0; i < NIT; i++) {
            const int s = i % NSTAGE;
            MBARRIER_WAIT_PARITY(bEmpty + 8 * s, pp);

#pragma unroll
            for (int m = 0; m < 4; m++) {
                const int row = r0 + m * 32;
                const float4* px = (const float4*)(xrow0 + (size_t)(m * 32) * DIM
                                                   + (size_t)i * KC);
                float4 f0 = px[0], f1 = px[1], f2 = px[2], f3 = px[3];
                float fv[16];
                *(float4*)(fv + 0)  = f0; *(float4*)(fv + 4)  = f1;
                *(float4*)(fv + 8)  = f2; *(float4*)(fv + 12) = f3;
                uint32_t hp[8], lp[8];
#pragma unroll
                for (int q = 0; q < 8; q++) {
                    __half2 h = __float22half2_rn(make_float2(fv[2*q], fv[2*q+1]));
                    float2 g = __half22float2(h);
                    __half2 l = __float22half2_rn(
                        make_float2((fv[2*q] - g.x) * 2048.0f,
                                    (fv[2*q+1] - g.y) * 2048.0f));
                    hp[q] = *(uint32_t*)&h;
                    lp[q] = *(uint32_t*)&l;
                }
                const uint32_t o0 = SW128((uint32_t)(row * 128 + kq * 2));
                const uint32_t o1 = SW128((uint32_t)(row * 128 + kq * 2 + 16));
                char* dh = smem + s * BUF_B + OFF_XH;
                char* dl = smem + s * BUF_B + OFF_XL;
                *(uint4*)(dh + o0) = make_uint4(hp[0], hp[1], hp[2], hp[3]);
                *(uint4*)(dh + o1) = make_uint4(hp[4], hp[5], hp[6], hp[7]);
                *(uint4*)(dl + o0) = make_uint4(lp[0], lp[1], lp[2], lp[3]);
                *(uint4*)(dl + o1) = make_uint4(lp[4], lp[5], lp[6], lp[7]);
            }
            MBARRIER_ARRIVE(bFull + 8 * s);
            if (s == NSTAGE - 1) pp ^= 1;
        }
    } else {
        // ================= CONSUMER (wid 0..11) =============================
        const bool isLo   = (wid >= 8);
        const int mt      = wid & 1;
        const int rowbase = mt * 64;
        const int cg      = isLo ? ((wid >> 1) & 1) : (wid >> 1);
        const int nbase   = cg * 32;
        const int n8base  = cg * 4;

        const int g  = lane >> 3;
        const int lr = lane & 7;
        const uint32_t rowA = (uint32_t)(rowbase + (g & 1) * 8 + lr) * 128;
        const uint32_t kx   = (uint32_t)(((g >> 1) ^ lr) << 4);

        float acc[4][4][4];
#pragma unroll
        for (int a = 0; a < 4; a++)
#pragma unroll
            for (int b = 0; b < 4; b++)
#pragma unroll
                for (int c = 0; c < 4; c++) acc[a][b][c] = 0.0f;

        int pc = 0;

        if (!isLo) {
            // ---- HI: xh * wh, M64 x N32 ----
            const unsigned char* pB = g_whf + n8base * 1024 + lane * 16;
            uint4 bf[4][2];
            auto ldB = [&](int chunk, int p) {
                const unsigned char* b = pB + (size_t)chunk * 16384 + p * 512;
#pragma unroll
                for (int t = 0; t < 4; t++)
                    bf[t][p] = *(const uint4*)(b + t * 1024);
            };
            ldB(0, 0); ldB(0, 1);

#pragma unroll 1
            for (int i = 0; i < NIT; i++) {
                const int s = i % NSTAGE;
                MBARRIER_WAIT_PARITY(bFull + 8 * s, pc);
                const uint32_t aB = sb + s * BUF_B + OFF_XH + rowA;

                uint32_t aa[2][4];
                ldsm4(aa[0], aB + kx);          // group 0: ks0, mi0
#pragma unroll
                for (int gr = 0; gr < 16; gr++) {
                    const int ks = gr >> 2, mi = gr & 3;
                    if (gr == 8)  ldB(i + 1, 0);    // bf[.][0] dead after ks1
                    if (gr < 15) {
                        const int g2 = gr + 1;
                        ldsm4(aa[(gr + 1) & 1],
                              aB + (g2 & 3) * 2048 + ((uint32_t)((g2 >> 2) * 32) ^ kx));
                    }
#pragma unroll
                    for (int t = 0; t < 4; t++) {
                        const uint4 bv = bf[t][ks >> 1];
                        const uint32_t b0 = (ks & 1) ? bv.z : bv.x;
                        const uint32_t b1 = (ks & 1) ? bv.w : bv.y;
                        mma16816(acc[mi][t], aa[gr & 1], b0, b1);
                    }
                }
                ldB(i + 1, 1);                       // bf[.][1] for next iter

                MBARRIER_ARRIVE(bEmpty + 8 * s);
                if (s == NSTAGE - 1) pc ^= 1;
            }
        } else {
            // ---- LO: xh*wl + xl*wh, M64 x N32, 8 ks-steps/iter ----
            // 4-deep fragment window: 8 steps/iter % 4 == 0 -> slot phase is
            // stationary (fw[st%4] always holds global step i*8+st).
            const unsigned char* pL  = g_wlf  + n8base * 1024 + lane * 8;
            const unsigned char* pH2 = g_whf2 + n8base * 1024 + lane * 8;
            uint2 fw[4][4];
            auto ldF = [&](int slot, int chunk, int st) {
                const int term = st >> 2, ks = st & 3;
                const unsigned char* b = (term ? pH2 : pL)
                                         + (size_t)chunk * 8192 + ks * 256;
#pragma unroll
                for (int t = 0; t < 4; t++)
                    fw[slot][t] = *(const uint2*)(b + t * 1024);
            };
            ldF(0, 0, 0); ldF(1, 0, 1); ldF(2, 0, 2); ldF(3, 0, 3);

#pragma unroll 1
            for (int i = 0; i < NIT; i++) {
                const int s4 = i % NSTAGE;
                MBARRIER_WAIT_PARITY(bFull + 8 * s4, pc);
                const uint32_t ahB = sb + s4 * BUF_B + OFF_XH + rowA;
                const uint32_t alB = sb + s4 * BUF_B + OFF_XL + rowA;

#pragma unroll
                for (int st = 0; st < 8; st++) {
                    const int term = st >> 2, ks = st & 3;
                    const uint32_t ko = ((uint32_t)(ks * 32)) ^ kx;
                    const uint32_t aBs = term ? alB : ahB;
                    uint32_t av[2][4];
                    ldsm4(av[0], aBs + ko);
#pragma unroll
                    for (int mi = 0; mi < 4; mi++) {
                        if (mi < 3) ldsm4(av[(mi + 1) & 1], aBs + (mi + 1) * 2048 + ko);
#pragma unroll
                        for (int t = 0; t < 4; t++)
                            mma16816(acc[mi][t], av[mi & 1],
                                     fw[st & 3][t].x, fw[st & 3][t].y);
                    }
                    // refill slot st&3 with global step (i*8+st)+4
                    if (st < 4) ldF(st & 3, i, st + 4);
                    else        ldF(st & 3, i + 1, st - 4);
                }

                MBARRIER_ARRIVE(bEmpty + 8 * s4);
                if (s4 == NSTAGE - 1) pc ^= 1;
            }
        }

        // stash accs to smem
        __syncthreads();
        float* sc = (float*)smem;                    // [128][129]
        float* lo = (float*)(smem + EPI_LO);         // [128][65]
        {
            float* dst = isLo ? lo : sc;
            const int stride = isLo ? 65 : 129;
            const int r4 = lane >> 2, c2 = (lane & 3) * 2;
#pragma unroll
            for (int mi = 0; mi < 4; mi++)
#pragma unroll
                for (int n8 = 0; n8 < 4; n8++) {
                    int row = rowbase + mi * 16 + r4;
                    int col = nbase + n8 * 8 + c2;
                    dst[row * stride + col]           = acc[mi][n8][0];
                    dst[row * stride + col + 1]       = acc[mi][n8][1];
                    dst[(row + 8) * stride + col]     = acc[mi][n8][2];
                    dst[(row + 8) * stride + col + 1] = acc[mi][n8][3];
                }
        }
    }
    if (wid >= 12) __syncthreads();   // producers join the pre-stash barrier
    __syncthreads();                  // stash complete

    // ---- epilogue: per-token routing (16 warps x 8 tokens) ----
    float* sc = (float*)smem;
    float* lo = (float*)(smem + EPI_LO);
    const float u_a = usage[lane], u_b = usage[lane + 32];
    const float utot = wsum(u_a + u_b);
    const float lbs  = 0.1f / (utot + 1e-6f);
    const float lbp_a = u_a * lbs, lbp_b = u_b * lbs;
    const float tclip = fmaxf(temp[0], 0.1f);
    const float cb1a = cap_b1[lane],  cb1b = cap_b1[lane + 32];
    const float ga   = ln_g[lane],    gb   = ln_g[lane + 32];
    const float ba   = ln_b[lane],    bb   = ln_b[lane + 32];
    const float w2a  = cap_w2[lane],  w2b  = cap_w2[lane + 32];
    const float b2   = cap_b2[0];
    const float INV2048 = 4.8828125e-4f;

#pragma unroll 1
    for (int j = 0; j < 8; j++) {
        const int tl = wid * 8 + j;
        const float* srow = sc + tl * 129;
        const float* lrow = lo + tl * 65;
        const float s_a = srow[lane]      + lrow[lane]      * INV2048;
        const float s_b = srow[lane + 32] + lrow[lane + 32] * INV2048;
        const float h_a = srow[64 + lane] + cb1a;
        const float h_b = srow[96 + lane] + cb1b;

        const float mu  = wsum(h_a + h_b) * (1.0f / 64.0f);
        const float msq = wsum(h_a * h_a + h_b * h_b) * (1.0f / 64.0f);
        const float rstd = rsqrtf(msq - mu * mu + 1e-5f);
        const float na = (h_a - mu) * rstd * ga + ba;
        const float nb = (h_b - mu) * rstd * gb + bb;
        const float ge_a = 0.5f * na * (1.0f + erff(na * 0.70710678118654752f));
        const float ge_b = 0.5f * nb * (1.0f + erff(nb * 0.70710678118654752f));
        const float z = wsum(ge_a * w2a + ge_b * w2b) + b2;
        const float cap = 1.0f / (1.0f + expf(-z));
        const float scale = cap * tclip;

        const float gta = (s_a - lbp_a) * scale;
        const float gtb = (s_b - lbp_b) * scale;

        float v1, v2; int i1, i2;
        if (better(gta, lane, gtb, lane + 32)) { v1 = gta; i1 = lane;      v2 = gtb; i2 = lane + 32; }
        else                                   { v1 = gtb; i1 = lane + 32; v2 = gta; i2 = lane; }
#pragma unroll
        for (int o = 16; o; o >>= 1) {
            float ov1 = __shfl_xor_sync(0xffffffffu, v1, o);
            int   oi1 = __shfl_xor_sync(0xffffffffu, i1, o);
            float ov2 = __shfl_xor_sync(0xffffffffu, v2, o);
            int   oi2 = __shfl_xor_sync(0xffffffffu, i2, o);
            if (better(ov1, oi1, v1, i1)) {
                float c2v; int c2i;
                if (better(v1, i1, ov2, oi2)) { c2v = v1; c2i = i1; }
                else                          { c2v = ov2; c2i = oi2; }
                v1 = ov1; i1 = oi1; v2 = c2v; i2 = c2i;
            } else if (better(ov1, oi1, v2, i2)) {
                v2 = ov1; i2 = oi1;
            }
        }
        const float inv = 1.0f / (v1 + v2 + 1e-6f);
        const size_t ob = (size_t)(tok0 + tl) * 64;
        out[ob + lane]      = (lane == i1)      ? v1 * inv : ((lane == i2)      ? v2 * inv : 0.0f);
        out[ob + lane + 32] = (lane + 32 == i1) ? v1 * inv : ((lane + 32 == i2) ? v2 * inv : 0.0f);
    }
}

// ---------------- launch ----------------
extern "C" void kernel_launch(void* const* d_in, const int* in_sizes, int n_in,
                              void* d_out, int out_size) {
    const float* x      = (const float*)d_in[0];
    const float* gate_w = (const float*)d_in[1];
    const float* cap_w1 = (const float*)d_in[2];
    const float* cap_b1 = (const float*)d_in[3];
    const float* ln_g   = (const float*)d_in[4];
    const float* ln_b   = (const float*)d_in[5];
    const float* cap_w2 = (const float*)d_in[6];
    const float* cap_b2 = (const float*)d_in[7];
    const float* temp   = (const float*)d_in[8];
    const float* usage  = (const float*)d_in[9];
    float* out = (float*)d_out;

    cudaFuncSetAttribute(router_kernel,
                         cudaFuncAttributeMaxDynamicSharedMemorySize, SMEM_SZ);

    prep_kernel<<<(NOUT * DIM) / 256, 256>>>(gate_w, cap_w1);
    router_kernel<<<NTOK / MT, 512, SMEM_SZ>>>(x, cap_b1, ln_g, ln_b, cap_w2,
                                               cap_b2, temp, usage, out);
}

// round 9
// speedup vs baseline: 1.0771x; 1.0771x over previous
#include <cuda_runtime.h>
#include <cuda_fp16.h>
#include <cstdint>

// ---------------------------------------------------------------------------
// FlashMoERouter on GB300 (sm_103a) — HMMA mma.sync, fp16 2-way split.
// R9: R6 core (W via cp.async smem + ldsm; warp-specialized mbarrier ring)
//     + consumer fragment software pipelining (1 step ahead, ping-pong)
//     + per-warp K rotation.
// ---------------------------------------------------------------------------

#define SW128(o) ((o) ^ (((o) >> 3) & 0x70))

static constexpr int NTOK   = 16384;
static constexpr int DIM    = 4096;
static constexpr int NOUT   = 128;
static constexpr int NEXP   = 64;
static constexpr int MT     = 128;
static constexpr int KC     = 64;
static constexpr int NIT    = DIM / KC;     // 64
static constexpr int TILE_B = 128 * 128;    // 16KB

static constexpr int OFF_XH = 0;
static constexpr int OFF_XL = 16384;
static constexpr int OFF_WH = 32768;
static constexpr int OFF_WL = 49152;
static constexpr int BUF_B  = 65536;
static constexpr int NSTAGE = 3;
static constexpr int OFF_BAR = NSTAGE * BUF_B;      // 196608
static constexpr int SMEM_SZ = OFF_BAR + 64;
static constexpr int EPI_LO  = 66048;               // lo[128][65] after sc[128][129]

__device__ __align__(16) unsigned char g_wh[NIT * TILE_B];
__device__ __align__(16) unsigned char g_wl[NIT * TILE_B];

// ---------------- helpers ----------------
__device__ __forceinline__ uint32_t smem_u32(const void* p) {
    uint32_t a;
    asm("{ .reg .u64 t; cvta.to.shared.u64 t, %1; cvt.u32.u64 %0, t; }"
        : "=r"(a) : "l"(p));
    return a;
}
__device__ __forceinline__ void cp_async16(uint32_t s, const void* g) {
    asm volatile("cp.async.cg.shared.global [%0], [%1], 16;" :: "r"(s), "l"(g) : "memory");
}
#define CP_COMMIT() asm volatile("cp.async.commit_group;" ::: "memory")
#define CP_WAIT0()  asm volatile("cp.async.wait_group 0;" ::: "memory")

#define MBARRIER_INIT(addr, cnt) \
    asm volatile("mbarrier.init.shared.b64 [%0], %1;" :: "r"(addr), "r"(cnt) : "memory")
#define MBARRIER_ARRIVE(addr) \
    asm volatile("mbarrier.arrive.shared.b64 _, [%0];" :: "r"(addr) : "memory")
#define MBARRIER_WAIT_PARITY(addr, par) do {                                        \
    uint32_t _m = (addr), _p = (par), _d;                                           \
    asm volatile("{ .reg .pred p; mbarrier.try_wait.parity.acquire.cta.shared::cta.b64 p, [%1], %2; selp.b32 %0,1,0,p; }" \
                 : "=r"(_d) : "r"(_m), "r"(_p) : "memory");                         \
    if (!_d) {                                                                      \
        asm volatile("{ .reg .pred P;\n"                                            \
            "WL_%=: mbarrier.try_wait.parity.acquire.cta.shared::cta.b64 P, [%0], %1, 0x989680;\n" \
            "@P bra WD_%=;\n bra WL_%=;\n WD_%=: }"                                 \
            :: "r"(_m), "r"(_p) : "memory");                                        \
    }                                                                               \
} while (0)

__device__ __forceinline__ void ldsm4(uint32_t* r, uint32_t addr) {
    asm volatile("ldmatrix.sync.aligned.m8n8.x4.shared.b16 {%0,%1,%2,%3}, [%4];"
                 : "=r"(r[0]), "=r"(r[1]), "=r"(r[2]), "=r"(r[3]) : "r"(addr));
}
__device__ __forceinline__ void mma16816(float* d, const uint32_t* a,
                                         uint32_t b0, uint32_t b1) {
    asm volatile(
        "mma.sync.aligned.m16n8k16.row.col.f32.f16.f16.f32 "
        "{%0,%1,%2,%3}, {%4,%5,%6,%7}, {%8,%9}, {%0,%1,%2,%3};"
        : "+f"(d[0]), "+f"(d[1]), "+f"(d[2]), "+f"(d[3])
        : "r"(a[0]), "r"(a[1]), "r"(a[2]), "r"(a[3]), "r"(b0), "r"(b1));
}
__device__ __forceinline__ float wsum(float v) {
#pragma unroll
    for (int o = 16; o; o >>= 1) v += __shfl_xor_sync(0xffffffffu, v, o);
    return v;
}
__device__ __forceinline__ bool better(float v, int i, float w, int j) {
    return (v > w) || (v == w && i < j);
}

// ---------------- prep: split W into swizzled fp16 tiles ----------------
__global__ void prep_kernel(const float* __restrict__ gate_w,
                            const float* __restrict__ cap_w1) {
    int idx = blockIdx.x * blockDim.x + threadIdx.x;
    if (idx >= NOUT * DIM) return;
    int n = idx >> 12;
    int k = idx & (DIM - 1);
    float w = (n < NEXP) ? gate_w[n * DIM + k] : cap_w1[(n - NEXP) * DIM + k];
    __half wh = __float2half_rn(w);
    float res = (w - __half2float(wh)) * 2048.0f;
    __half wl = __float2half_rn(res);
    int t = k >> 6, kk = k & 63;
    int off = SW128(n * 128 + kk * 2);
    *(__half*)(g_wh + t * TILE_B + off) = wh;
    *(__half*)(g_wl + t * TILE_B + off) = wl;
}

// ---------------- main kernel: 512 threads ----------------
__global__ void __launch_bounds__(512, 1)
router_kernel(const float* __restrict__ x,
              const float* __restrict__ cap_b1, const float* __restrict__ ln_g,
              const float* __restrict__ ln_b,   const float* __restrict__ cap_w2,
              const float* __restrict__ cap_b2, const float* __restrict__ temp,
              const float* __restrict__ usage,  float* __restrict__ out) {
    extern __shared__ char smem[];
    const uint32_t sb = smem_u32(smem);
    const int tid  = threadIdx.x;
    const int wid  = tid >> 5;
    const int lane = tid & 31;
    const int tok0 = blockIdx.x * MT;

    const uint32_t bFull  = sb + OFF_BAR;         // full[s]  at +8*s
    const uint32_t bEmpty = sb + OFF_BAR + 32;    // empty[s] at +8*s

    if (tid == 0) {
#pragma unroll
        for (int s = 0; s < NSTAGE; s++) {
            MBARRIER_INIT(bFull + 8 * s, 128);    // producer threads
            MBARRIER_INIT(bEmpty + 8 * s, 384);   // consumer threads
        }
    }
    __syncthreads();

    if (wid >= 12) {
        // ================= PRODUCER (wid 12..15, 128 threads) ===============
        const int pt = tid - 384;
        const int r0 = pt >> 2;
        const int kq = (pt & 3) * 16;
        const float* xrow0 = x + (size_t)(tok0 + r0) * DIM + kq;

        int pp = 1;
#pragma unroll 1
        for (int i = 0; i < NIT; i++) {
            const int s = i % NSTAGE;
            MBARRIER_WAIT_PARITY(bEmpty + 8 * s, pp);
            const uint32_t stg = sb + s * BUF_B;

            // W tiles: 16 cp.async per thread
            {
                const unsigned char* whs = g_wh + i * TILE_B;
                const unsigned char* wls = g_wl + i * TILE_B;
#pragma unroll
                for (int t = 0; t < 8; t++) {
                    int gidx = (pt + t * 128) * 16;
                    cp_async16(stg + OFF_WH + gidx, whs + gidx);
                    cp_async16(stg + OFF_WL + gidx, wls + gidx);
                }
                CP_COMMIT();
            }

            // x: 4 rows x 16 floats -> split -> swizzled STS
#pragma unroll
            for (int m = 0; m < 4; m++) {
                const int row = r0 + m * 32;
                const float4* px = (const float4*)(xrow0 + (size_t)(m * 32) * DIM
                                                   + (size_t)i * KC);
                float4 f0 = px[0], f1 = px[1], f2 = px[2], f3 = px[3];
                float fv[16];
                *(float4*)(fv + 0)  = f0; *(float4*)(fv + 4)  = f1;
                *(float4*)(fv + 8)  = f2; *(float4*)(fv + 12) = f3;
                uint32_t hp[8], lp[8];
#pragma unroll
                for (int q = 0; q < 8; q++) {
                    __half2 h = __float22half2_rn(make_float2(fv[2*q], fv[2*q+1]));
                    float2 g = __half22float2(h);
                    __half2 l = __float22half2_rn(
                        make_float2((fv[2*q] - g.x) * 2048.0f,
                                    (fv[2*q+1] - g.y) * 2048.0f));
                    hp[q] = *(uint32_t*)&h;
                    lp[q] = *(uint32_t*)&l;
                }
                const uint32_t o0 = SW128((uint32_t)(row * 128 + kq * 2));
                const uint32_t o1 = SW128((uint32_t)(row * 128 + kq * 2 + 16));
                char* dh = smem + s * BUF_B + OFF_XH;
                char* dl = smem + s * BUF_B + OFF_XL;
                *(uint4*)(dh + o0) = make_uint4(hp[0], hp[1], hp[2], hp[3]);
                *(uint4*)(dh + o1) = make_uint4(hp[4], hp[5], hp[6], hp[7]);
                *(uint4*)(dl + o0) = make_uint4(lp[0], lp[1], lp[2], lp[3]);
                *(uint4*)(dl + o1) = make_uint4(lp[4], lp[5], lp[6], lp[7]);
            }

            CP_WAIT0();
            MBARRIER_ARRIVE(bFull + 8 * s);
            if (s == NSTAGE - 1) pp ^= 1;
        }
    } else {
        // ================= CONSUMER (wid 0..11) =============================
        const bool isLo   = (wid >= 8);
        const int mt      = wid & 1;
        const int rowbase = mt * 64;
        const int cg      = isLo ? ((wid >> 1) & 1) : (wid >> 1);
        const int nbase   = cg * 32;

        const int g  = lane >> 3;
        const int lr = lane & 7;
        const uint32_t rowA = (uint32_t)(rowbase + (g & 1) * 8 + lr) * 128;
        const uint32_t rowB = (uint32_t)(nbase   + (g & 1) * 8 + lr) * 128;
        const uint32_t kx   = (uint32_t)(((g >> 1) ^ lr) << 4);

        float acc[4][4][4];
#pragma unroll
        for (int a = 0; a < 4; a++)
#pragma unroll
            for (int b = 0; b < 4; b++)
#pragma unroll
                for (int c = 0; c < 4; c++) acc[a][b][c] = 0.0f;

        int pc = 0;
        uint32_t af[2][4][4], bf[2][2][4];

        if (!isLo) {
            // ---- HI: xh * wh, M64 x N32, 4 ks-steps, pipelined 1 ahead ----
            const int krot = (wid >> 1) & 3;
#pragma unroll 1
            for (int i = 0; i < NIT; i++) {
                const int s = i % NSTAGE;
                MBARRIER_WAIT_PARITY(bFull + 8 * s, pc);
                const uint32_t aB = sb + s * BUF_B + OFF_XH + rowA;
                const uint32_t bB = sb + s * BUF_B + OFF_WH + rowB;

                {
                    const uint32_t ko = ((uint32_t)((krot & 3) * 32)) ^ kx;
#pragma unroll
                    for (int mi = 0; mi < 4; mi++) ldsm4(af[0][mi], aB + mi * 2048 + ko);
                    ldsm4(bf[0][0], bB + ko);
                    ldsm4(bf[0][1], bB + 2048 + ko);
                }
#pragma unroll
                for (int j = 0; j < 4; j++) {
                    const int cur = j & 1, nxt = cur ^ 1;
                    if (j < 3) {
                        const uint32_t kon =
                            ((uint32_t)((((j + 1 + krot) & 3)) * 32)) ^ kx;
#pragma unroll
                        for (int mi = 0; mi < 4; mi++)
                            ldsm4(af[nxt][mi], aB + mi * 2048 + kon);
                        ldsm4(bf[nxt][0], bB + kon);
                        ldsm4(bf[nxt][1], bB + 2048 + kon);
                    }
#pragma unroll
                    for (int mi = 0; mi < 4; mi++)
#pragma unroll
                        for (int nj = 0; nj < 2; nj++) {
                            mma16816(acc[mi][2*nj],   af[cur][mi],
                                     bf[cur][nj][0], bf[cur][nj][2]);
                            mma16816(acc[mi][2*nj+1], af[cur][mi],
                                     bf[cur][nj][1], bf[cur][nj][3]);
                        }
                }
                MBARRIER_ARRIVE(bEmpty + 8 * s);
                if (s == NSTAGE - 1) pc ^= 1;
            }
        } else {
            // ---- LO: xh*wl + xl*wh, 8 steps/iter, pipelined 1 ahead ----
            const int stRot = (wid & 3) * 2;
#pragma unroll 1
            for (int i = 0; i < NIT; i++) {
                const int s = i % NSTAGE;
                MBARRIER_WAIT_PARITY(bFull + 8 * s, pc);
                const uint32_t base = sb + s * BUF_B;
                const uint32_t ahB = base + OFF_XH + rowA;
                const uint32_t alB = base + OFF_XL + rowA;
                const uint32_t whB = base + OFF_WH + rowB;
                const uint32_t wlB = base + OFF_WL + rowB;

                {
                    const int sp = stRot & 7;
                    const uint32_t aB0 = (sp >> 2) ? alB : ahB;
                    const uint32_t bB0 = (sp >> 2) ? whB : wlB;
                    const uint32_t ko  = ((uint32_t)((sp & 3) * 32)) ^ kx;
#pragma unroll
                    for (int mi = 0; mi < 4; mi++) ldsm4(af[0][mi], aB0 + mi * 2048 + ko);
                    ldsm4(bf[0][0], bB0 + ko);
                    ldsm4(bf[0][1], bB0 + 2048 + ko);
                }
#pragma unroll
                for (int st = 0; st < 8; st++) {
                    const int cur = st & 1, nxt = cur ^ 1;
                    if (st < 7) {
                        const int sp = (st + 1 + stRot) & 7;
                        const uint32_t aBn = (sp >> 2) ? alB : ahB;
                        const uint32_t bBn = (sp >> 2) ? whB : wlB;
                        const uint32_t ko  = ((uint32_t)((sp & 3) * 32)) ^ kx;
#pragma unroll
                        for (int mi = 0; mi < 4; mi++)
                            ldsm4(af[nxt][mi], aBn + mi * 2048 + ko);
                        ldsm4(bf[nxt][0], bBn + ko);
                        ldsm4(bf[nxt][1], bBn + 2048 + ko);
                    }
#pragma unroll
                    for (int mi = 0; mi < 4; mi++)
#pragma unroll
                        for (int nj = 0; nj < 2; nj++) {
                            mma16816(acc[mi][2*nj],   af[cur][mi],
                                     bf[cur][nj][0], bf[cur][nj][2]);
                            mma16816(acc[mi][2*nj+1], af[cur][mi],
                                     bf[cur][nj][1], bf[cur][nj][3]);
                        }
                }
                MBARRIER_ARRIVE(bEmpty + 8 * s);
                if (s == NSTAGE - 1) pc ^= 1;
            }
        }

        // stash accs to smem
        __syncthreads();
        float* sc = (float*)smem;                    // [128][129]
        float* lo = (float*)(smem + EPI_LO);         // [128][65]
        {
            float* dst = isLo ? lo : sc;
            const int stride = isLo ? 65 : 129;
            const int r4 = lane >> 2, c2 = (lane & 3) * 2;
#pragma unroll
            for (int mi = 0; mi < 4; mi++)
#pragma unroll
                for (int n8 = 0; n8 < 4; n8++) {
                    int row = rowbase + mi * 16 + r4;
                    int col = nbase + n8 * 8 + c2;
                    dst[row * stride + col]           = acc[mi][n8][0];
                    dst[row * stride + col + 1]       = acc[mi][n8][1];
                    dst[(row + 8) * stride + col]     = acc[mi][n8][2];
                    dst[(row + 8) * stride + col + 1] = acc[mi][n8][3];
                }
        }
    }
    if (wid >= 12) __syncthreads();   // producers join the pre-stash barrier
    __syncthreads();                  // stash complete

    // ---- epilogue: per-token routing (16 warps x 8 tokens) ----
    float* sc = (float*)smem;
    float* lo = (float*)(smem + EPI_LO);
    const float u_a = usage[lane], u_b = usage[lane + 32];
    const float utot = wsum(u_a + u_b);
    const float lbs  = 0.1f / (utot + 1e-6f);
    const float lbp_a = u_a * lbs, lbp_b = u_b * lbs;
    const float tclip = fmaxf(temp[0], 0.1f);
    const float cb1a = cap_b1[lane],  cb1b = cap_b1[lane + 32];
    const float ga   = ln_g[lane],    gb   = ln_g[lane + 32];
    const float ba   = ln_b[lane],    bb   = ln_b[lane + 32];
    const float w2a  = cap_w2[lane],  w2b  = cap_w2[lane + 32];
    const float b2   = cap_b2[0];
    const float INV2048 = 4.8828125e-4f;

#pragma unroll 1
    for (int j = 0; j < 8; j++) {
        const int tl = wid * 8 + j;
        const float* srow = sc + tl * 129;
        const float* lrow = lo + tl * 65;
        const float s_a = srow[lane]      + lrow[lane]      * INV2048;
        const float s_b = srow[lane + 32] + lrow[lane + 32] * INV2048;
        const float h_a = srow[64 + lane] + cb1a;
        const float h_b = srow[96 + lane] + cb1b;

        const float mu  = wsum(h_a + h_b) * (1.0f / 64.0f);
        const float msq = wsum(h_a * h_a + h_b * h_b) * (1.0f / 64.0f);
        const float rstd = rsqrtf(msq - mu * mu + 1e-5f);
        const float na = (h_a - mu) * rstd * ga + ba;
        const float nb = (h_b - mu) * rstd * gb + bb;
        const float ge_a = 0.5f * na * (1.0f + erff(na * 0.70710678118654752f));
        const float ge_b = 0.5f * nb * (1.0f + erff(nb * 0.70710678118654752f));
        const float z = wsum(ge_a * w2a + ge_b * w2b) + b2;
        const float cap = 1.0f / (1.0f + expf(-z));
        const float scale = cap * tclip;

        const float gta = (s_a - lbp_a) * scale;
        const float gtb = (s_b - lbp_b) * scale;

        float v1, v2; int i1, i2;
        if (better(gta, lane, gtb, lane + 32)) { v1 = gta; i1 = lane;      v2 = gtb; i2 = lane + 32; }
        else                                   { v1 = gtb; i1 = lane + 32; v2 = gta; i2 = lane; }
#pragma unroll
        for (int o = 16; o; o >>= 1) {
            float ov1 = __shfl_xor_sync(0xffffffffu, v1, o);
            int   oi1 = __shfl_xor_sync(0xffffffffu, i1, o);
            float ov2 = __shfl_xor_sync(0xffffffffu, v2, o);
            int   oi2 = __shfl_xor_sync(0xffffffffu, i2, o);
            if (better(ov1, oi1, v1, i1)) {
                float c2v; int c2i;
                if (better(v1, i1, ov2, oi2)) { c2v = v1; c2i = i1; }
                else                          { c2v = ov2; c2i = oi2; }
                v1 = ov1; i1 = oi1; v2 = c2v; i2 = c2i;
            } else if (better(ov1, oi1, v2, i2)) {
                v2 = ov1; i2 = oi1;
            }
        }
        const float inv = 1.0f / (v1 + v2 + 1e-6f);
        const size_t ob = (size_t)(tok0 + tl) * 64;
        out[ob + lane]      = (lane == i1)      ? v1 * inv : ((lane == i2)      ? v2 * inv : 0.0f);
        out[ob + lane + 32] = (lane + 32 == i1) ? v1 * inv : ((lane + 32 == i2) ? v2 * inv : 0.0f);
    }
}

// ---------------- launch ----------------
extern "C" void kernel_launch(void* const* d_in, const int* in_sizes, int n_in,
                              void* d_out, int out_size) {
    const float* x      = (const float*)d_in[0];
    const float* gate_w = (const float*)d_in[1];
    const float* cap_w1 = (const float*)d_in[2];
    const float* cap_b1 = (const float*)d_in[3];
    const float* ln_g   = (const float*)d_in[4];
    const float* ln_b   = (const float*)d_in[5];
    const float* cap_w2 = (const float*)d_in[6];
    const float* cap_b2 = (const float*)d_in[7];
    const float* temp   = (const float*)d_in[8];
    const float* usage  = (const float*)d_in[9];
    float* out = (float*)d_out;

    cudaFuncSetAttribute(router_kernel,
                         cudaFuncAttributeMaxDynamicSharedMemorySize, SMEM_SZ);

    prep_kernel<<<(NOUT * DIM) / 256, 256>>>(gate_w, cap_w1);
    router_kernel<<<NTOK / MT, 512, SMEM_SZ>>>(x, cap_b1, ln_g, ln_b, cap_w2,
                                               cap_b2, temp, usage, out);
}

// round 10
// speedup vs baseline: 1.1630x; 1.0797x over previous
#include <cuda_runtime.h>
#include <cuda_fp16.h>
#include <cstdint>

// ---------------------------------------------------------------------------
// FlashMoERouter on GB300 (sm_103a) — HMMA mma.sync, fp16 2-way split.
// R10: 8 fat consumer warps (M64xN64, shared A-fragments, 128 HMMA each)
//      + 4 producer warps; 384 threads; mbarrier ring (3 stages).
// ---------------------------------------------------------------------------

#define SW128(o) ((o) ^ (((o) >> 3) & 0x70))

static constexpr int NTOK   = 16384;
static constexpr int DIM    = 4096;
static constexpr int NOUT   = 128;
static constexpr int NEXP   = 64;
static constexpr int MT     = 128;
static constexpr int KC     = 64;
static constexpr int NIT    = DIM / KC;     // 64
static constexpr int TILE_B = 128 * 128;    // 16KB

static constexpr int OFF_XH = 0;
static constexpr int OFF_XL = 16384;
static constexpr int OFF_WH = 32768;
static constexpr int OFF_WL = 49152;
static constexpr int BUF_B  = 65536;
static constexpr int NSTAGE = 3;
static constexpr int OFF_BAR = NSTAGE * BUF_B;      // 196608
static constexpr int SMEM_SZ = OFF_BAR + 64;
static constexpr int EPI_LO1 = 66048;               // lo1[128][65]
static constexpr int EPI_LO2 = 99328;               // lo2[128][65]

__device__ __align__(16) unsigned char g_wh[NIT * TILE_B];
__device__ __align__(16) unsigned char g_wl[NIT * TILE_B];

// ---------------- helpers ----------------
__device__ __forceinline__ uint32_t smem_u32(const void* p) {
    uint32_t a;
    asm("{ .reg .u64 t; cvta.to.shared.u64 t, %1; cvt.u32.u64 %0, t; }"
        : "=r"(a) : "l"(p));
    return a;
}
__device__ __forceinline__ void cp_async16(uint32_t s, const void* g) {
    asm volatile("cp.async.cg.shared.global [%0], [%1], 16;" :: "r"(s), "l"(g) : "memory");
}
#define CP_COMMIT() asm volatile("cp.async.commit_group;" ::: "memory")
#define CP_WAIT0()  asm volatile("cp.async.wait_group 0;" ::: "memory")

#define MBARRIER_INIT(addr, cnt) \
    asm volatile("mbarrier.init.shared.b64 [%0], %1;" :: "r"(addr), "r"(cnt) : "memory")
#define MBARRIER_ARRIVE(addr) \
    asm volatile("mbarrier.arrive.shared.b64 _, [%0];" :: "r"(addr) : "memory")
#define MBARRIER_WAIT_PARITY(addr, par) do {                                        \
    uint32_t _m = (addr), _p = (par), _d;                                           \
    asm volatile("{ .reg .pred p; mbarrier.try_wait.parity.acquire.cta.shared::cta.b64 p, [%1], %2; selp.b32 %0,1,0,p; }" \
                 : "=r"(_d) : "r"(_m), "r"(_p) : "memory");                         \
    if (!_d) {                                                                      \
        asm volatile("{ .reg .pred P;\n"                                            \
            "WL_%=: mbarrier.try_wait.parity.acquire.cta.shared::cta.b64 P, [%0], %1, 0x989680;\n" \
            "@P bra WD_%=;\n bra WL_%=;\n WD_%=: }"                                 \
            :: "r"(_m), "r"(_p) : "memory");                                        \
    }                                                                               \
} while (0)

__device__ __forceinline__ void ldsm4(uint32_t* r, uint32_t addr) {
    asm volatile("ldmatrix.sync.aligned.m8n8.x4.shared.b16 {%0,%1,%2,%3}, [%4];"
                 : "=r"(r[0]), "=r"(r[1]), "=r"(r[2]), "=r"(r[3]) : "r"(addr));
}
__device__ __forceinline__ void mma16816(float* d, const uint32_t* a,
                                         uint32_t b0, uint32_t b1) {
    asm volatile(
        "mma.sync.aligned.m16n8k16.row.col.f32.f16.f16.f32 "
        "{%0,%1,%2,%3}, {%4,%5,%6,%7}, {%8,%9}, {%0,%1,%2,%3};"
        : "+f"(d[0]), "+f"(d[1]), "+f"(d[2]), "+f"(d[3])
        : "r"(a[0]), "r"(a[1]), "r"(a[2]), "r"(a[3]), "r"(b0), "r"(b1));
}
__device__ __forceinline__ float wsum(float v) {
#pragma unroll
    for (int o = 16; o; o >>= 1) v += __shfl_xor_sync(0xffffffffu, v, o);
    return v;
}
__device__ __forceinline__ bool better(float v, int i, float w, int j) {
    return (v > w) || (v == w && i < j);
}

// ---------------- prep: split W into swizzled fp16 tiles ----------------
__global__ void prep_kernel(const float* __restrict__ gate_w,
                            const float* __restrict__ cap_w1) {
    int idx = blockIdx.x * blockDim.x + threadIdx.x;
    if (idx >= NOUT * DIM) return;
    int n = idx >> 12;
    int k = idx & (DIM - 1);
    float w = (n < NEXP) ? gate_w[n * DIM + k] : cap_w1[(n - NEXP) * DIM + k];
    __half wh = __float2half_rn(w);
    float res = (w - __half2float(wh)) * 2048.0f;
    __half wl = __float2half_rn(res);
    int t = k >> 6, kk = k & 63;
    int off = SW128(n * 128 + kk * 2);
    *(__half*)(g_wh + t * TILE_B + off) = wh;
    *(__half*)(g_wl + t * TILE_B + off) = wl;
}

// ---------------- main kernel: 384 threads (8 consumers + 4 producers) -----
__global__ void __launch_bounds__(384, 1)
router_kernel(const float* __restrict__ x,
              const float* __restrict__ cap_b1, const float* __restrict__ ln_g,
              const float* __restrict__ ln_b,   const float* __restrict__ cap_w2,
              const float* __restrict__ cap_b2, const float* __restrict__ temp,
              const float* __restrict__ usage,  float* __restrict__ out) {
    extern __shared__ char smem[];
    const uint32_t sb = smem_u32(smem);
    const int tid  = threadIdx.x;
    const int wid  = tid >> 5;
    const int lane = tid & 31;
    const int tok0 = blockIdx.x * MT;

    const uint32_t bFull  = sb + OFF_BAR;         // full[s]  at +8*s
    const uint32_t bEmpty = sb + OFF_BAR + 32;    // empty[s] at +8*s

    if (tid == 0) {
#pragma unroll
        for (int s = 0; s < NSTAGE; s++) {
            MBARRIER_INIT(bFull + 8 * s, 128);    // producer threads
            MBARRIER_INIT(bEmpty + 8 * s, 256);   // consumer threads
        }
    }
    __syncthreads();

    if (wid >= 8) {
        // ================= PRODUCER (wid 8..11, 128 threads) ================
        const int pt = tid - 256;
        const int r0 = pt >> 2;
        const int kq = (pt & 3) * 16;
        const float* xrow0 = x + (size_t)(tok0 + r0) * DIM + kq;

        int pp = 1;
#pragma unroll 1
        for (int i = 0; i < NIT; i++) {
            const int s = i % NSTAGE;
            MBARRIER_WAIT_PARITY(bEmpty + 8 * s, pp);
            const uint32_t stg = sb + s * BUF_B;

            // W tiles: 16 cp.async per thread
            {
                const unsigned char* whs = g_wh + i * TILE_B;
                const unsigned char* wls = g_wl + i * TILE_B;
#pragma unroll
                for (int t = 0; t < 8; t++) {
                    int gidx = (pt + t * 128) * 16;
                    cp_async16(stg + OFF_WH + gidx, whs + gidx);
                    cp_async16(stg + OFF_WL + gidx, wls + gidx);
                }
                CP_COMMIT();
            }

            // x: 4 rows x 16 floats -> split -> swizzled STS
#pragma unroll
            for (int m = 0; m < 4; m++) {
                const int row = r0 + m * 32;
                const float4* px = (const float4*)(xrow0 + (size_t)(m * 32) * DIM
                                                   + (size_t)i * KC);
                float4 f0 = px[0], f1 = px[1], f2 = px[2], f3 = px[3];
                float fv[16];
                *(float4*)(fv + 0)  = f0; *(float4*)(fv + 4)  = f1;
                *(float4*)(fv + 8)  = f2; *(float4*)(fv + 12) = f3;
                uint32_t hp[8], lp[8];
#pragma unroll
                for (int q = 0; q < 8; q++) {
                    __half2 h = __float22half2_rn(make_float2(fv[2*q], fv[2*q+1]));
                    float2 g = __half22float2(h);
                    __half2 l = __float22half2_rn(
                        make_float2((fv[2*q] - g.x) * 2048.0f,
                                    (fv[2*q+1] - g.y) * 2048.0f));
                    hp[q] = *(uint32_t*)&h;
                    lp[q] = *(uint32_t*)&l;
                }
                const uint32_t o0 = SW128((uint32_t)(row * 128 + kq * 2));
                const uint32_t o1 = SW128((uint32_t)(row * 128 + kq * 2 + 16));
                char* dh = smem + s * BUF_B + OFF_XH;
                char* dl = smem + s * BUF_B + OFF_XL;
                *(uint4*)(dh + o0) = make_uint4(hp[0], hp[1], hp[2], hp[3]);
                *(uint4*)(dh + o1) = make_uint4(hp[4], hp[5], hp[6], hp[7]);
                *(uint4*)(dl + o0) = make_uint4(lp[0], lp[1], lp[2], lp[3]);
                *(uint4*)(dl + o1) = make_uint4(lp[4], lp[5], lp[6], lp[7]);
            }

            CP_WAIT0();
            MBARRIER_ARRIVE(bFull + 8 * s);
            if (s == NSTAGE - 1) pp ^= 1;
        }
    } else {
        // ================= CONSUMER (wid 0..7): M64 x N64 each ==============
        // p = wid>>1: 0 = hi cols 0-63 (xh*wh), 1 = hi cols 64-127 (xh*wh),
        //             2 = loT1 (xh*wl, cols 0-63), 3 = loT2 (xl*wh, cols 0-63)
        const int mt      = wid & 1;
        const int p       = wid >> 1;
        const int rowbase = mt * 64;
        const int aOff    = (p == 3) ? OFF_XL : OFF_XH;
        const int bOff    = (p == 2) ? OFF_WL : OFF_WH;
        const int nbase   = (p == 1) ? 64 : 0;

        const int g  = lane >> 3;
        const int lr = lane & 7;
        const uint32_t rowA = (uint32_t)(rowbase + (g & 1) * 8 + lr) * 128;
        const uint32_t rowB = (uint32_t)(nbase   + (g & 1) * 8 + lr) * 128;
        const uint32_t kx   = (uint32_t)(((g >> 1) ^ lr) << 4);

        float acc[4][8][4];
#pragma unroll
        for (int a = 0; a < 4; a++)
#pragma unroll
            for (int b = 0; b < 8; b++)
#pragma unroll
                for (int c = 0; c < 4; c++) acc[a][b][c] = 0.0f;

        int pc = 0;
#pragma unroll 1
        for (int i = 0; i < NIT; i++) {
            const int s = i % NSTAGE;
            MBARRIER_WAIT_PARITY(bFull + 8 * s, pc);
            const uint32_t aB = sb + s * BUF_B + aOff + rowA;
            const uint32_t bB = sb + s * BUF_B + bOff + rowB;

#pragma unroll
            for (int ks = 0; ks < 4; ks++) {
                // per-warp K rotation spreads smem access phases
                const uint32_t ko = ((uint32_t)(((ks + wid) & 3) * 32)) ^ kx;
                uint32_t a[4][4], b[4][4];
#pragma unroll
                for (int mi = 0; mi < 4; mi++) ldsm4(a[mi], aB + mi * 2048 + ko);
#pragma unroll
                for (int nj = 0; nj < 4; nj++) ldsm4(b[nj], bB + nj * 2048 + ko);
#pragma unroll
                for (int mi = 0; mi < 4; mi++)
#pragma unroll
                    for (int nj = 0; nj < 4; nj++) {
                        mma16816(acc[mi][2*nj],   a[mi], b[nj][0], b[nj][2]);
                        mma16816(acc[mi][2*nj+1], a[mi], b[nj][1], b[nj][3]);
                    }
            }
            MBARRIER_ARRIVE(bEmpty + 8 * s);
            if (s == NSTAGE - 1) pc ^= 1;
        }

        // stash accs to smem
        __syncthreads();
        float* sc  = (float*)smem;                   // [128][129]
        float* lo1 = (float*)(smem + EPI_LO1);       // [128][65]
        float* lo2 = (float*)(smem + EPI_LO2);       // [128][65]
        {
            float* dst; int stride, colbase;
            if (p == 0)      { dst = sc;  stride = 129; colbase = 0;  }
            else if (p == 1) { dst = sc;  stride = 129; colbase = 64; }
            else if (p == 2) { dst = lo1; stride = 65;  colbase = 0;  }
            else             { dst = lo2; stride = 65;  colbase = 0;  }
            const int r4 = lane >> 2, c2 = (lane & 3) * 2;
#pragma unroll
            for (int mi = 0; mi < 4; mi++)
#pragma unroll
                for (int n8 = 0; n8 < 8; n8++) {
                    int row = rowbase + mi * 16 + r4;
                    int col = colbase + n8 * 8 + c2;
                    dst[row * stride + col]           = acc[mi][n8][0];
                    dst[row * stride + col + 1]       = acc[mi][n8][1];
                    dst[(row + 8) * stride + col]     = acc[mi][n8][2];
                    dst[(row + 8) * stride + col + 1] = acc[mi][n8][3];
                }
        }
    }
    if (wid >= 8) __syncthreads();    // producers join the pre-stash barrier
    __syncthreads();                  // stash complete

    // ---- epilogue: per-token routing (12 warps x up to 11 tokens) ----
    float* sc  = (float*)smem;
    float* lo1 = (float*)(smem + EPI_LO1);
    float* lo2 = (float*)(smem + EPI_LO2);
    const float u_a = usage[lane], u_b = usage[lane + 32];
    const float utot = wsum(u_a + u_b);
    const float lbs  = 0.1f / (utot + 1e-6f);
    const float lbp_a = u_a * lbs, lbp_b = u_b * lbs;
    const float tclip = fmaxf(temp[0], 0.1f);
    const float cb1a = cap_b1[lane],  cb1b = cap_b1[lane + 32];
    const float ga   = ln_g[lane],    gb   = ln_g[lane + 32];
    const float ba   = ln_b[lane],    bb   = ln_b[lane + 32];
    const float w2a  = cap_w2[lane],  w2b  = cap_w2[lane + 32];
    const float b2   = cap_b2[0];
    const float INV2048 = 4.8828125e-4f;

#pragma unroll 1
    for (int j = 0; j < 11; j++) {
        const int tl = j * 12 + wid;
        if (tl >= MT) break;
        const float* srow  = sc  + tl * 129;
        const float* l1row = lo1 + tl * 65;
        const float* l2row = lo2 + tl * 65;
        const float s_a = srow[lane]      + (l1row[lane]      + l2row[lane])      * INV2048;
        const float s_b = srow[lane + 32] + (l1row[lane + 32] + l2row[lane + 32]) * INV2048;
        const float h_a = srow[64 + lane] + cb1a;
        const float h_b = srow[96 + lane] + cb1b;

        const float mu  = wsum(h_a + h_b) * (1.0f / 64.0f);
        const float msq = wsum(h_a * h_a + h_b * h_b) * (1.0f / 64.0f);
        const float rstd = rsqrtf(msq - mu * mu + 1e-5f);
        const float na = (h_a - mu) * rstd * ga + ba;
        const float nb = (h_b - mu) * rstd * gb + bb;
        const float ge_a = 0.5f * na * (1.0f + erff(na * 0.70710678118654752f));
        const float ge_b = 0.5f * nb * (1.0f + erff(nb * 0.70710678118654752f));
        const float z = wsum(ge_a * w2a + ge_b * w2b) + b2;
        const float cap = 1.0f / (1.0f + expf(-z));
        const float scale = cap * tclip;

        const float gta = (s_a - lbp_a) * scale;
        const float gtb = (s_b - lbp_b) * scale;

        float v1, v2; int i1, i2;
        if (better(gta, lane, gtb, lane + 32)) { v1 = gta; i1 = lane;      v2 = gtb; i2 = lane + 32; }
        else                                   { v1 = gtb; i1 = lane + 32; v2 = gta; i2 = lane; }
#pragma unroll
        for (int o = 16; o; o >>= 1) {
            float ov1 = __shfl_xor_sync(0xffffffffu, v1, o);
            int   oi1 = __shfl_xor_sync(0xffffffffu, i1, o);
            float ov2 = __shfl_xor_sync(0xffffffffu, v2, o);
            int   oi2 = __shfl_xor_sync(0xffffffffu, i2, o);
            if (better(ov1, oi1, v1, i1)) {
                float c2v; int c2i;
                if (better(v1, i1, ov2, oi2)) { c2v = v1; c2i = i1; }
                else                          { c2v = ov2; c2i = oi2; }
                v1 = ov1; i1 = oi1; v2 = c2v; i2 = c2i;
            } else if (better(ov1, oi1, v2, i2)) {
                v2 = ov1; i2 = oi1;
            }
        }
        const float inv = 1.0f / (v1 + v2 + 1e-6f);
        const size_t ob = (size_t)(tok0 + tl) * 64;
        out[ob + lane]      = (lane == i1)      ? v1 * inv : ((lane == i2)      ? v2 * inv : 0.0f);
        out[ob + lane + 32] = (lane + 32 == i1) ? v1 * inv : ((lane + 32 == i2) ? v2 * inv : 0.0f);
    }
}

// ---------------- launch ----------------
extern "C" void kernel_launch(void* const* d_in, const int* in_sizes, int n_in,
                              void* d_out, int out_size) {
    const float* x      = (const float*)d_in[0];
    const float* gate_w = (const float*)d_in[1];
    const float* cap_w1 = (const float*)d_in[2];
    const float* cap_b1 = (const float*)d_in[3];
    const float* ln_g   = (const float*)d_in[4];
    const float* ln_b   = (const float*)d_in[5];
    const float* cap_w2 = (const float*)d_in[6];
    const float* cap_b2 = (const float*)d_in[7];
    const float* temp   = (const float*)d_in[8];
    const float* usage  = (const float*)d_in[9];
    float* out = (float*)d_out;

    cudaFuncSetAttribute(router_kernel,
                         cudaFuncAttributeMaxDynamicSharedMemorySize, SMEM_SZ);

    prep_kernel<<<(NOUT * DIM) / 256, 256>>>(gate_w, cap_w1);
    router_kernel<<<NTOK / MT, 384, SMEM_SZ>>>(x, cap_b1, ln_g, ln_b, cap_w2,
                                               cap_b2, temp, usage, out);
}